// round 11
// baseline (speedup 1.0000x reference)
#include <cuda_runtime.h>
#include <math.h>

// Problem dims
#define B_ 128
#define T_ 256
#define D_ 128
#define Z_ 64
#define E_ 512
#define NCOL 2048
#define KT 32

#define NCTA 128
#define NTHREADS 512

// ---------------- scratch layout (floats) ----------------
#define HB 65536
#define OFF_STATE 64
#define OFF_EH0 (OFF_STATE)
#define OFF_EH1 (OFF_EH0 + 2*HB)
#define OFF_DH0 (OFF_EH1 + 2*HB)
#define OFF_DH1 (OFF_DH0 + 2*HB)
#define OFF_EC0 (OFF_DH1 + 2*HB)
#define OFF_EC1 (OFF_EC0 + HB)
#define OFF_DC0 (OFF_EC1 + HB)
#define OFF_DC1 (OFF_DC0 + HB)
#define STATE_END (OFF_DC1 + HB)
#define OFF_GU1 STATE_END
#define OFF_GUD0 (OFF_GU1 + 262144)
#define OFF_GUD1 (OFF_GUD0 + 262144)
#define OFF_SIGC (OFF_GUD1 + 262144)    // 128*128: -sig(c_prev)
#define OFF_ZBUF (OFF_SIGC + 16384)     // 128*64
#define OFF_WC   (OFF_ZBUF + 8192)      // 128*2048: W1+W2
#define SCRATCH_TOTAL (OFF_WC + 262144)

__device__ float g_scratch[SCRATCH_TOTAL];
__device__ float g_prex[(size_t)B_ * T_ * NCOL];   // x@(W1+W2) for all t

__device__ __forceinline__ float sigf(float x) { return 1.0f / (1.0f + expf(-x)); }

#define FMA2(acc_, a_, b_) \
    asm("fma.rn.f32x2 %0, %1, %2, %0;" : "+l"(acc_) : "l"(a_), "l"(b_))

__device__ __forceinline__ unsigned long long splat2(float w) {
    unsigned long long r; unsigned int b = __float_as_uint(w);
    asm("mov.b64 %0, {%1, %1};" : "=l"(r) : "r"(b));
    return r;
}
__device__ __forceinline__ float lo2(unsigned long long v) { return __uint_as_float((unsigned)v); }
__device__ __forceinline__ float hi2(unsigned long long v) { return __uint_as_float((unsigned)(v >> 32)); }

struct VaeParams {
    const float *x, *eps;
    const float *enc0_W, *enc0_U, *enc0_b;
    const float *enc1_W, *enc1_U, *enc1_b;
    const float *mu_W, *mu_b, *sig_W, *sig_b;
    const float *dec0_W, *dec0_U, *dec0_b;
    const float *dec1_W, *dec1_U, *dec1_b;
    const float *out_W, *out_b;
    float *o_dec, *o_sig, *o_mu, *o_ls, *o_z;
};

// ---------------------------------------------------------------------------
// Grid barrier (state zeroed by the memset node every replay; co-residency
// guaranteed by cooperative launch, with plain-launch fallback).
// ---------------------------------------------------------------------------
__device__ __forceinline__ void grid_sync(int& lgen)
{
    int* bar = (int*)g_scratch;            // [0]=cnt, [1]=gen
    __threadfence();
    __syncthreads();
    if (threadIdx.x == 0) {
        volatile int* gen = bar + 1;
        int g = lgen;
        if (atomicAdd(bar, 1) == NCTA - 1) {
            *bar = 0;
            __threadfence();
            atomicExch((int*)(bar + 1), g + 1);
        } else {
            while (*gen <= g) { __nanosleep(64); }
        }
    }
    __syncthreads();
    __threadfence();
    lgen++;
}

// ---------------------------------------------------------------------------
// 64-row x 128-gate-col GEMM tile, 512 threads. Thread: 4 rows (2 f32x2
// pairs) x 4 gates. W duplicated in smem as (w,w) ullongs -> LDS.64, no
// splats in the inner loop. Register-prefetch double buffer.
// ---------------------------------------------------------------------------
__device__ __forceinline__ void gemm64w(
    const float* __restrict__ a1, const float* __restrict__ W1, int K1,
    const float* __restrict__ a2, const float* __restrict__ W2, int K2,
    int j0, int b0, unsigned long long acc[2][4],
    unsigned long long* w2_s, float* a_s)
{
    const int tid = threadIdx.x;
    const int ux  = tid & 31;
    const int rg  = tid >> 5;
    const int nt  = (K1 + K2) / KT;
    float wreg[8], areg[4];

    auto load_tile = [&](int t) {
        int kb = t * KT;
        const float* a = a1; const float* W = W1; int K = K1;
        if (kb >= K1) { a = a2; W = W2; K = K2; kb -= K1; }
        #pragma unroll
        for (int i = 0; i < 8; i++) {
            int idx = tid + i * 512;
            wreg[i] = W[(kb + (idx >> 7)) * NCOL + (((idx & 127) >> 5) * E_ + j0 + (idx & 31))];
        }
        #pragma unroll
        for (int i = 0; i < 4; i++) {
            int idx = tid + i * 512;
            areg[i] = a[(b0 + (idx >> 5)) * K + kb + (idx & 31)];
        }
    };

    load_tile(0);
    #pragma unroll 1
    for (int t = 0; t < nt; t++) {
        __syncthreads();
        #pragma unroll
        for (int i = 0; i < 8; i++) {
            int idx = tid + i * 512;
            w2_s[(idx >> 7) * 128 + (idx & 127)] = splat2(wreg[i]);
        }
        #pragma unroll
        for (int i = 0; i < 4; i++) {
            int idx = tid + i * 512;
            int kk = idx & 31, row = idx >> 5;
            a_s[kk * 64 + (((row >> 2) ^ (kk & 15)) << 2) + (row & 3)] = areg[i];
        }
        __syncthreads();
        if (t + 1 < nt) load_tile(t + 1);
        #pragma unroll 8
        for (int kk = 0; kk < KT; kk++) {
            ulonglong2 A = *(const ulonglong2*)(a_s + kk * 64 + ((rg ^ (kk & 15)) << 2));
            const unsigned long long* wk = w2_s + kk * 128 + ux;
            #pragma unroll
            for (int g = 0; g < 4; g++) {
                unsigned long long w2 = wk[g * 32];
                FMA2(acc[0][g], A.x, w2);
                FMA2(acc[1][g], A.y, w2);
            }
        }
    }
}

// ---------------------------------------------------------------------------
// Finish stage: 16 rows x 128 gate-cols per CTA (128 CTAs), 512 threads.
// Warp: gate-pair gp=rg&1, row-pair rp=rg>>1. Gate exchange through smem
// before the LSTM epilogue (gates split across warps during the GEMM).
// ---------------------------------------------------------------------------
__device__ __noinline__ void finish16w(
    const float* __restrict__ a, const float* __restrict__ W, int K,
    const float* __restrict__ pregate, const float* __restrict__ bias,
    float* __restrict__ h_out, float* __restrict__ c_state,
    unsigned long long* w2_s, float* a_s)
{
    const int tid = threadIdx.x;
    const int ux  = tid & 31;
    const int rg  = tid >> 5;
    const int gp  = rg & 1;
    const int rp  = rg >> 1;              // 0..7
    const int cta = blockIdx.x;
    const int j0  = (cta & 15) * 32;
    const int b0  = (cta >> 4) * 16;
    const int nt  = K / KT;
    unsigned long long acc[2] = {0ull, 0ull};
    float wreg[8], areg1;

    auto load_tile = [&](int t) {
        int kb = t * KT;
        #pragma unroll
        for (int i = 0; i < 8; i++) {
            int idx = tid + i * 512;
            wreg[i] = W[(kb + (idx >> 7)) * NCOL + (((idx & 127) >> 5) * E_ + j0 + (idx & 31))];
        }
        areg1 = a[(b0 + (tid & 15)) * K + kb + (tid >> 4)];
    };

    load_tile(0);
    #pragma unroll 1
    for (int t = 0; t < nt; t++) {
        __syncthreads();
        #pragma unroll
        for (int i = 0; i < 8; i++) {
            int idx = tid + i * 512;
            w2_s[(idx >> 7) * 128 + (idx & 127)] = splat2(wreg[i]);
        }
        {
            int kk = tid >> 4, row = tid & 15;
            a_s[kk * 16 + (((row >> 2) ^ (kk & 3)) << 2) + (row & 3)] = areg1;
        }
        __syncthreads();
        if (t + 1 < nt) load_tile(t + 1);
        #pragma unroll 8
        for (int kk = 0; kk < KT; kk++) {
            unsigned long long A = *(const unsigned long long*)(
                a_s + kk * 16 + (((rp >> 1) ^ (kk & 3)) << 2) + ((rp & 1) << 1));
            FMA2(acc[0], A, w2_s[kk * 128 + (2 * gp + 0) * 32 + ux]);
            FMA2(acc[1], A, w2_s[kk * 128 + (2 * gp + 1) * 32 + ux]);
        }
    }

    // gate exchange: alias w2_s (done reading it) as ex[4][8][32]
    __syncthreads();
    unsigned long long* ex = w2_s;
    ex[(2 * gp + 0) * 256 + rp * 32 + ux] = acc[0];
    ex[(2 * gp + 1) * 256 + rp * 32 + ux] = acc[1];
    __syncthreads();

    if (tid < 256) {
        const int ux2 = tid & 31;
        const int pr  = tid >> 5;         // 0..7
        const int j   = j0 + ux2;
        const int b   = b0 + 2 * pr;
        unsigned long long g0 = ex[0 * 256 + pr * 32 + ux2];
        unsigned long long g1 = ex[1 * 256 + pr * 32 + ux2];
        unsigned long long g2 = ex[2 * 256 + pr * 32 + ux2];
        unsigned long long g3 = ex[3 * 256 + pr * 32 + ux2];
        float b_i = bias[0 * E_ + j], b_f = bias[1 * E_ + j];
        float b_c = bias[2 * E_ + j], b_o = bias[3 * E_ + j];
        {
            const float* pg = pregate + (size_t)b * NCOL + j;
            float ig = sigf(lo2(g0) + b_i + pg[0 * E_]);
            float fg = sigf(lo2(g1) + b_f + pg[1 * E_]);
            float cg = tanhf(lo2(g2) + b_c + pg[2 * E_]);
            float og = sigf(lo2(g3) + b_o + pg[3 * E_]);
            float cn = fg * c_state[b * E_ + j] + ig * cg;
            c_state[b * E_ + j] = cn;
            h_out[b * E_ + j]   = og * tanhf(cn);
        }
        {
            const float* pg = pregate + (size_t)(b + 1) * NCOL + j;
            float ig = sigf(hi2(g0) + b_i + pg[0 * E_]);
            float fg = sigf(hi2(g1) + b_f + pg[1 * E_]);
            float cg = tanhf(hi2(g2) + b_c + pg[2 * E_]);
            float og = sigf(hi2(g3) + b_o + pg[3 * E_]);
            float cn = fg * c_state[(b + 1) * E_ + j] + ig * cg;
            c_state[(b + 1) * E_ + j] = cn;
            h_out[(b + 1) * E_ + j]   = og * tanhf(cn);
        }
    }
}

// ---------------------------------------------------------------------------
// Persistent kernel
// ---------------------------------------------------------------------------
__global__ void __launch_bounds__(NTHREADS, 1) vae_persistent(VaeParams p)
{
    __shared__ __align__(16) unsigned long long w2_s[KT * 128];  // 32 KB
    __shared__ __align__(16) float a_s[KT * 64];                 // 8 KB

    float* s = g_scratch;
    float* eh0[2] = { s + OFF_EH0, s + OFF_EH0 + HB };
    float* eh1[2] = { s + OFF_EH1, s + OFF_EH1 + HB };
    float* dh0[2] = { s + OFF_DH0, s + OFF_DH0 + HB };
    float* dh1[2] = { s + OFF_DH1, s + OFF_DH1 + HB };
    float* ec0  = s + OFF_EC0;
    float* ec1  = s + OFF_EC1;
    float* dc0  = s + OFF_DC0;
    float* dc1  = s + OFF_DC1;
    float* gU1  = s + OFF_GU1;
    float* gUd0 = s + OFF_GUD0;
    float* gUd1 = s + OFF_GUD1;
    float* sigc = s + OFF_SIGC;
    float* zbuf = s + OFF_ZBUF;
    float* Wc   = s + OFF_WC;

    const int cta = blockIdx.x;
    const int tid = threadIdx.x;
    const int ux  = tid & 31;
    const int rg  = tid >> 5;
    int lgen = 0;

    // ---- init: sigc = -sig(0) = -0.5 ; Wc = W1 + W2 ----
    {
        int idx = cta * NTHREADS + tid;
        if (idx < B_ * D_) sigc[idx] = -0.5f;
        #pragma unroll
        for (int i = 0; i < 4; i++) {
            int w = idx + i * 65536;               // 128*2048 = 262144
            Wc[w] = p.enc0_W[w] + p.enc0_W[128 * NCOL + w];
        }
    }
    grid_sync(lgen);

    // ---- prepass: prex[r,:] = x[r,:] @ Wc for all r = b*T+t ----
    #pragma unroll 1
    for (int tile = cta; tile < 8192; tile += NCTA) {
        const int r0 = (tile >> 4) * 64;
        const int j0 = (tile & 15) * 32;
        unsigned long long acc[2][4] = {};
        gemm64w(p.x, Wc, 128, nullptr, nullptr, 0, j0, r0, acc, w2_s, a_s);
        const int j = j0 + ux;
        #pragma unroll
        for (int pr = 0; pr < 2; pr++) {
            int r = r0 + 4 * rg + 2 * pr;
            #pragma unroll
            for (int g = 0; g < 4; g++) {
                g_prex[(size_t)r * NCOL + g * E_ + j]       = lo2(acc[pr][g]);
                g_prex[(size_t)(r + 1) * NCOL + g * E_ + j] = hi2(acc[pr][g]);
            }
        }
    }
    grid_sync(lgen);

    for (int t = 0; t < T_; t++) {
        const int pp = t & 1, q = pp ^ 1;

        // ---- Phase A: 4 recurrent gate-GEMMs (128 tiles = grid) ----
        {
            const int z   = cta >> 5;
            const int sub = cta & 31;
            const int b0  = (sub >> 4) * 64;
            const int j0  = (sub & 15) * 32;
            unsigned long long acc[2][4] = {};

            const float *ga1, *gW1, *ga2, *gW2; int gK1, gK2;
            if (z == 0)      { ga1 = eh1[pp]; gW1 = p.enc1_U; gK1 = E_; ga2 = nullptr; gW2 = nullptr; gK2 = 0; }
            else if (z == 1) { ga1 = dh0[pp]; gW1 = p.dec0_U; gK1 = E_; ga2 = nullptr; gW2 = nullptr; gK2 = 0; }
            else if (z == 2) { ga1 = dh1[pp]; gW1 = p.dec1_U; gK1 = E_; ga2 = nullptr; gW2 = nullptr; gK2 = 0; }
            else             { ga1 = eh0[pp]; gW1 = p.enc0_U; gK1 = E_;
                               ga2 = sigc;    gW2 = p.enc0_W + 128 * NCOL; gK2 = 128; }

            gemm64w(ga1, gW1, gK1, ga2, gW2, gK2, j0, b0, acc, w2_s, a_s);

            const int j = j0 + ux;
            if (z < 3) {
                float* o = (z == 0) ? gU1 : (z == 1) ? gUd0 : gUd1;
                #pragma unroll
                for (int pr = 0; pr < 2; pr++) {
                    int b = b0 + 4 * rg + 2 * pr;
                    #pragma unroll
                    for (int g = 0; g < 4; g++) {
                        o[(size_t)b * NCOL + g * E_ + j]       = lo2(acc[pr][g]);
                        o[(size_t)(b + 1) * NCOL + g * E_ + j] = hi2(acc[pr][g]);
                    }
                }
            } else {
                float b_i = p.enc0_b[0 * E_ + j];
                float b_f = p.enc0_b[1 * E_ + j];
                float b_c = p.enc0_b[2 * E_ + j];
                float b_o = p.enc0_b[3 * E_ + j];
                #pragma unroll
                for (int pr = 0; pr < 2; pr++) {
                    int b = b0 + 4 * rg + 2 * pr;
                    #pragma unroll
                    for (int h = 0; h < 2; h++) {
                        int bb = b + h;
                        const float* px = g_prex + (size_t)(bb * T_ + t) * NCOL + j;
                        float vi = h ? hi2(acc[pr][0]) : lo2(acc[pr][0]);
                        float vf = h ? hi2(acc[pr][1]) : lo2(acc[pr][1]);
                        float vc = h ? hi2(acc[pr][2]) : lo2(acc[pr][2]);
                        float vo = h ? hi2(acc[pr][3]) : lo2(acc[pr][3]);
                        float ig = sigf(vi + b_i + px[0 * E_]);
                        float fg = sigf(vf + b_f + px[1 * E_]);
                        float cg = tanhf(vc + b_c + px[2 * E_]);
                        float og = sigf(vo + b_o + px[3 * E_]);
                        float cn = fg * ec0[bb * E_ + j] + ig * cg;
                        ec0[bb * E_ + j] = cn;
                        eh0[q][bb * E_ + j] = og * tanhf(cn);
                    }
                }
            }
        }
        grid_sync(lgen);

        // ---- Phase B: enc1 finish ----
        finish16w(eh0[q], p.enc1_W, E_, gU1, p.enc1_b, eh1[q], ec1, w2_s, a_s);
        grid_sync(lgen);

        // ---- Phase C: latent (16 CTAs) ----
        if (cta < 16) {
            float* wc = (float*)w2_s;             // KT x 64
            const int j0 = (cta & 1) * 32;
            const int b0 = (cta >> 1) * 16;
            float acc[2][2] = {{0.f, 0.f}, {0.f, 0.f}};
            const float* a = eh1[q];
            for (int k0 = 0; k0 < E_; k0 += KT) {
                #pragma unroll
                for (int i = 0; i < 4; i++) {
                    int idx = tid + i * 512;
                    int kk = idx >> 6, lc = idx & 63;
                    int col = j0 + (lc & 31);
                    wc[kk * 64 + lc] = (lc & 32) ? p.sig_W[(k0 + kk) * Z_ + col]
                                                 : p.mu_W[(k0 + kk) * Z_ + col];
                }
                {
                    int row = tid >> 5, kk = tid & 31;
                    a_s[row * KT + kk] = a[(b0 + row) * E_ + k0 + kk];
                }
                __syncthreads();
                if (rg < 8) {
                    #pragma unroll
                    for (int kk = 0; kk < KT; kk++) {
                        float av0 = a_s[(rg * 2 + 0) * KT + kk];
                        float av1 = a_s[(rg * 2 + 1) * KT + kk];
                        float wm = wc[kk * 64 + ux];
                        float ws = wc[kk * 64 + 32 + ux];
                        acc[0][0] += av0 * wm; acc[0][1] += av0 * ws;
                        acc[1][0] += av1 * wm; acc[1][1] += av1 * ws;
                    }
                }
                __syncthreads();
            }
            if (rg < 8) {
                const int j = j0 + ux;
                #pragma unroll
                for (int r = 0; r < 2; r++) {
                    int b = b0 + rg * 2 + r;
                    float mu = acc[r][0] + p.mu_b[j];
                    float ls = acc[r][1] + p.sig_b[j];
                    float sg = expf(ls);
                    float zv = mu + sg * p.eps[((size_t)t * B_ + b) * Z_ + j];
                    size_t o = ((size_t)t * B_ + b) * Z_ + j;
                    p.o_sig[o] = sg;
                    p.o_mu[o]  = mu;
                    p.o_ls[o]  = ls;
                    p.o_z[o]   = zv;
                    zbuf[b * Z_ + j] = zv;
                }
            }
        }
        grid_sync(lgen);

        // ---- Phase D: dec0 finish (K=64) ----
        finish16w(zbuf, p.dec0_W, Z_, gUd0, p.dec0_b, dh0[q], dc0, w2_s, a_s);
        grid_sync(lgen);

        // ---- Phase E: dec1 finish ----
        finish16w(dh0[q], p.dec1_W, E_, gUd1, p.dec1_b, dh1[q], dc1, w2_s, a_s);
        grid_sync(lgen);

        // ---- Phase F: output + sigc for next step (32 CTAs) ----
        if (cta < 32) {
            float* wf = (float*)w2_s;             // KT x 32
            const int c0 = (cta & 3) * 32;
            const int b0 = (cta >> 2) * 16;
            float acc2[2] = {0.f, 0.f};
            const float* a = dh1[q];
            for (int k0 = 0; k0 < E_; k0 += KT) {
                #pragma unroll
                for (int i = 0; i < 2; i++) {
                    int idx = tid + i * 512;
                    wf[(idx >> 5) * 32 + (idx & 31)] = p.out_W[(k0 + (idx >> 5)) * D_ + c0 + (idx & 31)];
                }
                {
                    int row = tid >> 5, kk = tid & 31;
                    a_s[row * KT + kk] = a[(b0 + row) * E_ + k0 + kk];
                }
                __syncthreads();
                if (rg < 8) {
                    #pragma unroll
                    for (int kk = 0; kk < KT; kk++) {
                        float w = wf[kk * 32 + ux];
                        acc2[0] += a_s[(rg * 2 + 0) * KT + kk] * w;
                        acc2[1] += a_s[(rg * 2 + 1) * KT + kk] * w;
                    }
                }
                __syncthreads();
            }
            if (rg < 8) {
                const int j = c0 + ux;
                #pragma unroll
                for (int r = 0; r < 2; r++) {
                    int b = b0 + rg * 2 + r;
                    float ct = sigf(acc2[r] + p.out_b[j]);
                    p.o_dec[(size_t)b * T_ * D_ + (size_t)t * D_ + j] = ct;
                    sigc[b * D_ + j] = -sigf(ct);   // sigmoid of stored c_t: matches ref
                }
            }
        }
        grid_sync(lgen);
    }
}

extern "C" void kernel_launch(void* const* d_in, const int* in_sizes, int n_in,
                              void* d_out, int out_size)
{
    VaeParams p;
    p.x      = (const float*)d_in[0];
    p.eps    = (const float*)d_in[1];
    p.enc0_W = (const float*)d_in[2];
    p.enc0_U = (const float*)d_in[3];
    p.enc0_b = (const float*)d_in[4];
    p.enc1_W = (const float*)d_in[5];
    p.enc1_U = (const float*)d_in[6];
    p.enc1_b = (const float*)d_in[7];
    p.mu_W   = (const float*)d_in[8];
    p.mu_b   = (const float*)d_in[9];
    p.sig_W  = (const float*)d_in[10];
    p.sig_b  = (const float*)d_in[11];
    p.dec0_W = (const float*)d_in[12];
    p.dec0_U = (const float*)d_in[13];
    p.dec0_b = (const float*)d_in[14];
    p.dec1_W = (const float*)d_in[15];
    p.dec1_U = (const float*)d_in[16];
    p.dec1_b = (const float*)d_in[17];
    p.out_W  = (const float*)d_in[18];
    p.out_b  = (const float*)d_in[19];

    float* out = (float*)d_out;
    p.o_dec = out;
    p.o_sig = out + (size_t)B_ * T_ * D_;
    p.o_mu  = p.o_sig + (size_t)T_ * B_ * Z_;
    p.o_ls  = p.o_mu  + (size_t)T_ * B_ * Z_;
    p.o_z   = p.o_ls  + (size_t)T_ * B_ * Z_;

    float* s = nullptr;
    cudaGetSymbolAddress((void**)&s, g_scratch);

    cudaMemsetAsync(s, 0, sizeof(float) * (size_t)STATE_END, 0);

    void* kernelArgs[] = { (void*)&p };
    cudaError_t e = cudaLaunchCooperativeKernel(
        (void*)vae_persistent, dim3(NCTA), dim3(NTHREADS), kernelArgs, 0, (cudaStream_t)0);
    if (e != cudaSuccess) {
        (void)cudaGetLastError();
        vae_persistent<<<NCTA, NTHREADS>>>(p);
    }
}

// round 14
// speedup vs baseline: 1.2597x; 1.2597x over previous
#include <cuda_runtime.h>
#include <math.h>

// Problem dims
#define B_ 128
#define T_ 256
#define D_ 128
#define Z_ 64
#define E_ 512
#define NCOL 2048
#define KT 32

#define NCTA 128
#define NTHREADS 256

// ---------------- scratch layout (floats) ----------------
#define HB 65536
#define OFF_STATE 64
#define OFF_EH0 (OFF_STATE)
#define OFF_EH1 (OFF_EH0 + 2*HB)
#define OFF_DH0 (OFF_EH1 + 2*HB)
#define OFF_DH1 (OFF_DH0 + 2*HB)
#define OFF_EC0 (OFF_DH1 + 2*HB)
#define OFF_EC1 (OFF_EC0 + HB)
#define OFF_DC0 (OFF_EC1 + HB)
#define OFF_DC1 (OFF_DC0 + HB)
#define STATE_END (OFF_DC1 + HB)
#define OFF_GU1 STATE_END
#define OFF_GUD0 (OFF_GU1 + 262144)
#define OFF_GUD1 (OFF_GUD0 + 262144)
#define OFF_SIGC (OFF_GUD1 + 262144)    // 128*128: -sig(c_prev)
#define OFF_WC   (OFF_SIGC + 16384)     // 128*2048: W1+W2
#define SCRATCH_TOTAL (OFF_WC + 262144)

__device__ __align__(16) float g_scratch[SCRATCH_TOTAL];
__device__ __align__(16) float g_prex[(size_t)B_ * T_ * NCOL];   // x@(W1+W2)

__device__ __forceinline__ float sigf(float x) { return 1.0f / (1.0f + expf(-x)); }

#define FMA2(acc_, a_, b_) \
    asm("fma.rn.f32x2 %0, %1, %2, %0;" : "+l"(acc_) : "l"(a_), "l"(b_))

__device__ __forceinline__ unsigned long long splat2(float w) {
    unsigned long long r; unsigned int b = __float_as_uint(w);
    asm("mov.b64 %0, {%1, %1};" : "=l"(r) : "r"(b));
    return r;
}
__device__ __forceinline__ float lo2(unsigned long long v) { return __uint_as_float((unsigned)v); }
__device__ __forceinline__ float hi2(unsigned long long v) { return __uint_as_float((unsigned)(v >> 32)); }

#define CP_ASYNC16(dst_u32, src_ptr) \
    asm volatile("cp.async.cg.shared.global [%0], [%1], 16;" :: "r"(dst_u32), "l"(src_ptr))
#define CP_COMMIT() asm volatile("cp.async.commit_group;" ::: "memory")
#define CP_WAIT0()  asm volatile("cp.async.wait_group 0;" ::: "memory")

struct VaeParams {
    const float *x, *eps;
    const float *enc0_W, *enc0_U, *enc0_b;
    const float *enc1_W, *enc1_U, *enc1_b;
    const float *mu_W, *mu_b, *sig_W, *sig_b;
    const float *dec0_W, *dec0_U, *dec0_b;
    const float *dec1_W, *dec1_U, *dec1_b;
    const float *out_W, *out_b;
    float *o_dec, *o_sig, *o_mu, *o_ls, *o_z;
};

// ---------------------------------------------------------------------------
// Grid barrier (state zeroed by memset node each replay; co-residency via
// cooperative launch with plain fallback).
// ---------------------------------------------------------------------------
__device__ __forceinline__ void grid_sync(int& lgen)
{
    int* bar = (int*)g_scratch;            // [0]=cnt, [1]=gen
    __threadfence();
    __syncthreads();
    if (threadIdx.x == 0) {
        volatile int* gen = bar + 1;
        int g = lgen;
        if (atomicAdd(bar, 1) == NCTA - 1) {
            *bar = 0;
            __threadfence();
            atomicExch((int*)(bar + 1), g + 1);
        } else {
            while (*gen <= g) { __nanosleep(32); }
        }
    }
    __syncthreads();
    __threadfence();
    lgen++;
}

// smem layout (floats)
#define SM_W   0                       // 2 x KT x 128 = 8192
#define SM_A   8192                    // 2 x KT x 64  = 4096
#define SM_Z   12288                   // 16 x 65      = 1040
#define SM_TOTAL 13344

// cp.async one W k-tile (KT x 128 gate-grouped) into stage st.
__device__ __forceinline__ void issueW(
    float* smem, int st, const float* __restrict__ W, int kb, int j0, int tid)
{
    unsigned wb = (unsigned)__cvta_generic_to_shared(smem + SM_W + st * 4096);
    #pragma unroll
    for (int o = 0; o < 4; o++) {
        int idx = tid + o * 256;       // 0..1023
        int sgi = idx >> 3;            // 0..127 (kk,g) segments
        int l16 = idx & 7;
        int kk = sgi >> 2, g = sgi & 3;
        const float* src = W + (size_t)(kb + kk) * NCOL + g * E_ + j0 + l16 * 4;
        CP_ASYNC16(wb + ((kk * 128 + g * 32 + l16 * 4) << 2), src);
    }
    CP_COMMIT();
}

// ---------------------------------------------------------------------------
// 64-row x 128-gate-col GEMM, 256 thr. Thread: 8 rows (4 pairs) x 4 gates.
// W via cp.async double-buffer; a via register prefetch into swizzled smem.
// ---------------------------------------------------------------------------
__device__ __forceinline__ void gemm64(
    float* smem,
    const float* __restrict__ a1, const float* __restrict__ W1, int K1,
    const float* __restrict__ a2, const float* __restrict__ W2, int K2,
    int j0, int b0, unsigned long long acc[4][4])
{
    const int tid = threadIdx.x;
    const int ux  = tid & 31;
    const int rg  = tid >> 5;
    const int nt  = (K1 + K2) / KT;
    float areg[8];

    auto segp = [&](int tt, const float*& W, const float*& a, int& kb, int& K) {
        int kbt = tt * KT;
        if (kbt < K1) { W = W1; a = a1; kb = kbt; K = K1; }
        else          { W = W2; a = a2; kb = kbt - K1; K = K2; }
    };
    auto loadA = [&](const float* a, int kb, int K) {
        #pragma unroll
        for (int i = 0; i < 8; i++) {
            int idx = tid + i * 256;
            areg[i] = a[(size_t)(b0 + (idx >> 5)) * K + kb + (idx & 31)];
        }
    };

    { const float* W; const float* a; int kb, K; segp(0, W, a, kb, K);
      issueW(smem, 0, W, kb, j0, tid); loadA(a, kb, K); }

    #pragma unroll 1
    for (int tt = 0; tt < nt; tt++) {
        const int st = tt & 1;
        CP_WAIT0();
        float* as = smem + SM_A + st * 2048;
        #pragma unroll
        for (int i = 0; i < 8; i++) {
            int idx = tid + i * 256;
            int kk = idx & 31, row = idx >> 5;
            as[kk * 64 + (((row >> 2) ^ (kk & 15)) << 2) + (row & 3)] = areg[i];
        }
        __syncthreads();
        if (tt + 1 < nt) {
            const float* W; const float* a; int kb, K; segp(tt + 1, W, a, kb, K);
            issueW(smem, st ^ 1, W, kb, j0, tid);
            loadA(a, kb, K);
        }
        const float* ws = smem + SM_W + st * 4096;
        #pragma unroll 8
        for (int kk = 0; kk < KT; kk++) {
            const float* ak = as + kk * 64;
            const int sw = kk & 15;
            ulonglong2 A0 = *(const ulonglong2*)(ak + (((rg * 2 + 0) ^ sw) << 2));
            ulonglong2 A1 = *(const ulonglong2*)(ak + (((rg * 2 + 1) ^ sw) << 2));
            const float* wk = ws + kk * 128 + ux;
            #pragma unroll
            for (int g = 0; g < 4; g++) {
                unsigned long long w2 = splat2(wk[g * 32]);
                FMA2(acc[0][g], A0.x, w2);
                FMA2(acc[1][g], A0.y, w2);
                FMA2(acc[2][g], A1.x, w2);
                FMA2(acc[3][g], A1.y, w2);
            }
        }
    }
}

// ---------------------------------------------------------------------------
// Finish stage: 16 rows x 128 gate-cols, 256 thr, W via cp.async, a (gmem or
// smem) via register prefetch. arow0/astride let 'a' be local zloc smem.
// ---------------------------------------------------------------------------
__device__ __noinline__ void finish16(
    float* smem,
    const float* __restrict__ a, int arow0, int astride,
    const float* __restrict__ W, int K,
    const float* __restrict__ pregate, const float* __restrict__ bias,
    float* __restrict__ h_out, float* __restrict__ c_state,
    int j0, int b0)
{
    const int tid = threadIdx.x;
    const int ux  = tid & 31;
    const int rg  = tid >> 5;
    const int nt  = K / KT;
    unsigned long long acc[4] = {0ull, 0ull, 0ull, 0ull};
    float areg[2];

    auto loadA = [&](int kb) {
        #pragma unroll
        for (int i = 0; i < 2; i++) {
            int idx = tid + i * 256;
            areg[i] = a[(size_t)(arow0 + (idx & 15)) * astride + kb + (idx >> 4)];
        }
    };

    issueW(smem, 0, W, 0, j0, tid);
    loadA(0);

    #pragma unroll 1
    for (int tt = 0; tt < nt; tt++) {
        const int st = tt & 1;
        CP_WAIT0();
        float* as = smem + SM_A + st * 2048;
        #pragma unroll
        for (int i = 0; i < 2; i++) {
            int idx = tid + i * 256;
            int kk = idx >> 4, row = idx & 15;
            as[kk * 16 + (((row >> 2) ^ (kk & 3)) << 2) + (row & 3)] = areg[i];
        }
        __syncthreads();
        if (tt + 1 < nt) {
            issueW(smem, st ^ 1, W, (tt + 1) * KT, j0, tid);
            loadA((tt + 1) * KT);
        }
        const float* ws = smem + SM_W + st * 4096;
        #pragma unroll 8
        for (int kk = 0; kk < KT; kk++) {
            unsigned long long A = *(const unsigned long long*)(
                as + kk * 16 + (((rg >> 1) ^ (kk & 3)) << 2) + ((rg & 1) << 1));
            const float* wk = ws + kk * 128 + ux;
            #pragma unroll
            for (int g = 0; g < 4; g++) {
                unsigned long long w2 = splat2(wk[g * 32]);
                FMA2(acc[g], A, w2);
            }
        }
    }

    const int j = j0 + ux;
    const int b = b0 + rg * 2;
    float b_i = bias[0 * E_ + j], b_f = bias[1 * E_ + j];
    float b_c = bias[2 * E_ + j], b_o = bias[3 * E_ + j];
    {
        const float* pg = pregate + (size_t)b * NCOL + j;
        float ig = sigf(lo2(acc[0]) + b_i + pg[0 * E_]);
        float fg = sigf(lo2(acc[1]) + b_f + pg[1 * E_]);
        float cg = tanhf(lo2(acc[2]) + b_c + pg[2 * E_]);
        float og = sigf(lo2(acc[3]) + b_o + pg[3 * E_]);
        float cn = fg * c_state[b * E_ + j] + ig * cg;
        c_state[b * E_ + j] = cn;
        h_out[b * E_ + j]   = og * tanhf(cn);
    }
    {
        const float* pg = pregate + (size_t)(b + 1) * NCOL + j;
        float ig = sigf(hi2(acc[0]) + b_i + pg[0 * E_]);
        float fg = sigf(hi2(acc[1]) + b_f + pg[1 * E_]);
        float cg = tanhf(hi2(acc[2]) + b_c + pg[2 * E_]);
        float og = sigf(hi2(acc[3]) + b_o + pg[3 * E_]);
        float cn = fg * c_state[(b + 1) * E_ + j] + ig * cg;
        c_state[(b + 1) * E_ + j] = cn;
        h_out[(b + 1) * E_ + j]   = og * tanhf(cn);
    }
}

// ---------------------------------------------------------------------------
// Persistent kernel: prepass + T=256 recurrence, 5 phases/step.
// ---------------------------------------------------------------------------
__global__ void __launch_bounds__(NTHREADS, 1) vae_persistent(VaeParams p)
{
    __shared__ __align__(16) float smem[SM_TOTAL];

    float* s = g_scratch;
    float* eh0[2] = { s + OFF_EH0, s + OFF_EH0 + HB };
    float* eh1[2] = { s + OFF_EH1, s + OFF_EH1 + HB };
    float* dh0[2] = { s + OFF_DH0, s + OFF_DH0 + HB };
    float* dh1[2] = { s + OFF_DH1, s + OFF_DH1 + HB };
    float* ec0  = s + OFF_EC0;
    float* ec1  = s + OFF_EC1;
    float* dc0  = s + OFF_DC0;
    float* dc1  = s + OFF_DC1;
    float* gU1  = s + OFF_GU1;
    float* gUd0 = s + OFF_GUD0;
    float* gUd1 = s + OFF_GUD1;
    float* sigc = s + OFF_SIGC;
    float* Wc   = s + OFF_WC;
    float* zloc = smem + SM_Z;            // [16][65]

    const int cta = blockIdx.x;
    const int tid = threadIdx.x;
    const int ux  = tid & 31;
    const int rg  = tid >> 5;
    int lgen = 0;

    // ---- init: sigc = -0.5 ; Wc = W1 + W2 ----
    {
        int idx = cta * NTHREADS + tid;   // 0..32767
        if (idx < B_ * D_) sigc[idx] = -0.5f;
        #pragma unroll
        for (int i = 0; i < 8; i++) {
            int w = idx + i * 32768;      // 262144 total
            Wc[w] = p.enc0_W[w] + p.enc0_W[128 * NCOL + w];
        }
    }
    grid_sync(lgen);

    // ---- prepass: g_prex[r,:] = x[r,:] @ Wc  (r = b*T+t, 32768 rows) ----
    #pragma unroll 1
    for (int tile = cta; tile < 8192; tile += NCTA) {
        const int r0 = (tile >> 4) * 64;
        const int j0 = (tile & 15) * 32;
        unsigned long long acc[4][4] = {};
        gemm64(smem, p.x, Wc, 128, nullptr, nullptr, 0, j0, r0, acc);
        const int j = j0 + ux;
        #pragma unroll
        for (int pr = 0; pr < 4; pr++) {
            int r = r0 + rg * 8 + pr * 2;
            #pragma unroll
            for (int g = 0; g < 4; g++) {
                g_prex[(size_t)r * NCOL + g * E_ + j]       = lo2(acc[pr][g]);
                g_prex[(size_t)(r + 1) * NCOL + g * E_ + j] = hi2(acc[pr][g]);
            }
        }
        __syncthreads();
    }
    grid_sync(lgen);

    for (int t = 0; t < T_; t++) {
        const int pp = t & 1, q = pp ^ 1;

        // ---- Phase A: 4 recurrent gate-GEMMs (128 tiles = grid) ----
        {
            const int z   = cta >> 5;
            const int sub = cta & 31;
            const int b0  = (sub >> 4) * 64;
            const int j0  = (sub & 15) * 32;
            unsigned long long acc[4][4] = {};

            const float *ga1, *gW1, *ga2, *gW2; int gK1, gK2;
            if (z == 0)      { ga1 = eh1[pp]; gW1 = p.enc1_U; gK1 = E_; ga2 = nullptr; gW2 = nullptr; gK2 = 0; }
            else if (z == 1) { ga1 = dh0[pp]; gW1 = p.dec0_U; gK1 = E_; ga2 = nullptr; gW2 = nullptr; gK2 = 0; }
            else if (z == 2) { ga1 = dh1[pp]; gW1 = p.dec1_U; gK1 = E_; ga2 = nullptr; gW2 = nullptr; gK2 = 0; }
            else             { ga1 = eh0[pp]; gW1 = p.enc0_U; gK1 = E_;
                               ga2 = sigc;    gW2 = p.enc0_W + 128 * NCOL; gK2 = 128; }

            gemm64(smem, ga1, gW1, gK1, ga2, gW2, gK2, j0, b0, acc);

            const int j = j0 + ux;
            if (z < 3) {
                float* o = (z == 0) ? gU1 : (z == 1) ? gUd0 : gUd1;
                #pragma unroll
                for (int pr = 0; pr < 4; pr++) {
                    int b = b0 + rg * 8 + pr * 2;
                    #pragma unroll
                    for (int g = 0; g < 4; g++) {
                        o[(size_t)b * NCOL + g * E_ + j]       = lo2(acc[pr][g]);
                        o[(size_t)(b + 1) * NCOL + g * E_ + j] = hi2(acc[pr][g]);
                    }
                }
            } else {
                float b_i = p.enc0_b[0 * E_ + j];
                float b_f = p.enc0_b[1 * E_ + j];
                float b_c = p.enc0_b[2 * E_ + j];
                float b_o = p.enc0_b[3 * E_ + j];
                #pragma unroll
                for (int pr = 0; pr < 4; pr++) {
                    int b = b0 + rg * 8 + pr * 2;
                    #pragma unroll
                    for (int h = 0; h < 2; h++) {
                        int bb = b + h;
                        const float* px = g_prex + (size_t)(bb * T_ + t) * NCOL + j;
                        float vi = h ? hi2(acc[pr][0]) : lo2(acc[pr][0]);
                        float vf = h ? hi2(acc[pr][1]) : lo2(acc[pr][1]);
                        float vc = h ? hi2(acc[pr][2]) : lo2(acc[pr][2]);
                        float vo = h ? hi2(acc[pr][3]) : lo2(acc[pr][3]);
                        float ig = sigf(vi + b_i + px[0 * E_]);
                        float fg = sigf(vf + b_f + px[1 * E_]);
                        float cg = tanhf(vc + b_c + px[2 * E_]);
                        float og = sigf(vo + b_o + px[3 * E_]);
                        float cn = fg * ec0[bb * E_ + j] + ig * cg;
                        ec0[bb * E_ + j] = cn;
                        eh0[q][bb * E_ + j] = og * tanhf(cn);
                    }
                }
            }
        }
        grid_sync(lgen);

        // ---- Phase B: enc1 finish ----
        finish16(smem, eh0[q], (cta >> 4) * 16, E_, p.enc1_W, E_,
                 gU1, p.enc1_b, eh1[q], ec1, (cta & 15) * 32, (cta >> 4) * 16);
        grid_sync(lgen);

        // ---- Phase CD: latent (redundant per-CTA, 16 own rows) + dec0 finish ----
        {
            const int j0f = (cta & 15) * 32;
            const int b0f = (cta >> 4) * 16;
            // z-GEMM: 16 rows x (64 mu | 64 sig), K=512
            unsigned long long zacc[4] = {0ull, 0ull, 0ull, 0ull};
            const float* a = eh1[q];
            float* wz = smem + SM_W;                  // KT x 128 (stage 0)
            float* az = smem + SM_A;                  // KT x 16 swizzled
            for (int k0 = 0; k0 < E_; k0 += KT) {
                #pragma unroll
                for (int i = 0; i < 16; i++) {
                    int idx = tid + i * 256;
                    int kk = idx >> 7, lc = idx & 127;
                    const float* Wm = (lc & 64) ? p.sig_W : p.mu_W;
                    wz[kk * 128 + lc] = Wm[(k0 + kk) * Z_ + (lc & 63)];
                }
                #pragma unroll
                for (int i = 0; i < 2; i++) {
                    int idx = tid + i * 256;
                    int kk = idx >> 4, row = idx & 15;
                    az[kk * 16 + (((row >> 2) ^ (kk & 3)) << 2) + (row & 3)] =
                        a[(size_t)(b0f + row) * E_ + k0 + kk];
                }
                __syncthreads();
                #pragma unroll 8
                for (int kk = 0; kk < KT; kk++) {
                    unsigned long long A = *(const unsigned long long*)(
                        az + kk * 16 + (((rg >> 1) ^ (kk & 3)) << 2) + ((rg & 1) << 1));
                    const float* wk = wz + kk * 128;
                    FMA2(zacc[0], A, splat2(wk[ux]));          // mu c=ux
                    FMA2(zacc[1], A, splat2(wk[32 + ux]));     // mu c=ux+32
                    FMA2(zacc[2], A, splat2(wk[64 + ux]));     // sig c=ux
                    FMA2(zacc[3], A, splat2(wk[96 + ux]));     // sig c=ux+32
                }
                __syncthreads();
            }
            // epilogue: z = mu + exp(ls)*eps; store zloc; canonical CTA -> outputs
            const bool canon = (cta & 15) == 0;
            #pragma unroll
            for (int r = 0; r < 2; r++) {
                int row = 2 * rg + r;      // wait: zacc pairs rows (2rg,2rg+1)
                int b = b0f + row;
                #pragma unroll
                for (int ch = 0; ch < 2; ch++) {
                    int c = ux + 32 * ch;
                    float mu = (r ? hi2(zacc[ch]) : lo2(zacc[ch])) + p.mu_b[c];
                    float ls = (r ? hi2(zacc[2 + ch]) : lo2(zacc[2 + ch])) + p.sig_b[c];
                    float sg = expf(ls);
                    float zv = mu + sg * p.eps[((size_t)t * B_ + b) * Z_ + c];
                    zloc[row * 65 + c] = zv;
                    if (canon) {
                        size_t o = ((size_t)t * B_ + b) * Z_ + c;
                        p.o_sig[o] = sg;
                        p.o_mu[o]  = mu;
                        p.o_ls[o]  = ls;
                        p.o_z[o]   = zv;
                    }
                }
            }
            __syncthreads();
            // dec0 finish from local z
            finish16(smem, zloc, 0, 65, p.dec0_W, Z_,
                     gUd0, p.dec0_b, dh0[q], dc0, j0f, b0f);
        }
        grid_sync(lgen);

        // ---- Phase E: dec1 finish ----
        finish16(smem, dh0[q], (cta >> 4) * 16, E_, p.dec1_W, E_,
                 gUd1, p.dec1_b, dh1[q], dc1, (cta & 15) * 32, (cta >> 4) * 16);
        grid_sync(lgen);

        // ---- Phase F: out GEMM -> o_dec + sigc (32 CTAs) ----
        if (cta < 32) {
            float* wf = smem + SM_W;                  // KT x 32
            float* af = smem + SM_A;                  // 16 x KT natural
            const int c0 = (cta & 3) * 32;
            const int b0 = (cta >> 2) * 16;
            float acc2[2] = {0.f, 0.f};
            const float* a = dh1[q];
            for (int k0 = 0; k0 < E_; k0 += KT) {
                #pragma unroll
                for (int i = 0; i < 4; i++) {
                    int idx = tid + i * 256;
                    wf[(idx >> 5) * 32 + (idx & 31)] =
                        p.out_W[(k0 + (idx >> 5)) * D_ + c0 + (idx & 31)];
                }
                #pragma unroll
                for (int i = 0; i < 2; i++) {
                    int idx = tid + i * 256;
                    af[(idx >> 5) * KT + (idx & 31)] =
                        a[(size_t)(b0 + (idx >> 5)) * E_ + k0 + (idx & 31)];
                }
                __syncthreads();
                #pragma unroll
                for (int kk = 0; kk < KT; kk++) {
                    float w = wf[kk * 32 + ux];
                    acc2[0] += af[(rg * 2 + 0) * KT + kk] * w;
                    acc2[1] += af[(rg * 2 + 1) * KT + kk] * w;
                }
                __syncthreads();
            }
            const int j = c0 + ux;
            #pragma unroll
            for (int r = 0; r < 2; r++) {
                int b = b0 + rg * 2 + r;
                float ct = sigf(acc2[r] + p.out_b[j]);
                p.o_dec[(size_t)b * T_ * D_ + (size_t)t * D_ + j] = ct;
                sigc[b * D_ + j] = -sigf(ct);    // sigmoid of stored c_t: matches ref
            }
        }
        grid_sync(lgen);
    }
}

extern "C" void kernel_launch(void* const* d_in, const int* in_sizes, int n_in,
                              void* d_out, int out_size)
{
    VaeParams p;
    p.x      = (const float*)d_in[0];
    p.eps    = (const float*)d_in[1];
    p.enc0_W = (const float*)d_in[2];
    p.enc0_U = (const float*)d_in[3];
    p.enc0_b = (const float*)d_in[4];
    p.enc1_W = (const float*)d_in[5];
    p.enc1_U = (const float*)d_in[6];
    p.enc1_b = (const float*)d_in[7];
    p.mu_W   = (const float*)d_in[8];
    p.mu_b   = (const float*)d_in[9];
    p.sig_W  = (const float*)d_in[10];
    p.sig_b  = (const float*)d_in[11];
    p.dec0_W = (const float*)d_in[12];
    p.dec0_U = (const float*)d_in[13];
    p.dec0_b = (const float*)d_in[14];
    p.dec1_W = (const float*)d_in[15];
    p.dec1_U = (const float*)d_in[16];
    p.dec1_b = (const float*)d_in[17];
    p.out_W  = (const float*)d_in[18];
    p.out_b  = (const float*)d_in[19];

    float* out = (float*)d_out;
    p.o_dec = out;
    p.o_sig = out + (size_t)B_ * T_ * D_;
    p.o_mu  = p.o_sig + (size_t)T_ * B_ * Z_;
    p.o_ls  = p.o_mu  + (size_t)T_ * B_ * Z_;
    p.o_z   = p.o_ls  + (size_t)T_ * B_ * Z_;

    float* s = nullptr;
    cudaGetSymbolAddress((void**)&s, g_scratch);

    cudaMemsetAsync(s, 0, sizeof(float) * (size_t)STATE_END, 0);

    void* kernelArgs[] = { (void*)&p };
    cudaError_t e = cudaLaunchCooperativeKernel(
        (void*)vae_persistent, dim3(NCTA), dim3(NTHREADS), kernelArgs, 0, (cudaStream_t)0);
    if (e != cudaSuccess) {
        (void)cudaGetLastError();
        vae_persistent<<<NCTA, NTHREADS>>>(p);
    }
}